// round 17
// baseline (speedup 1.0000x reference)
#include <cuda_runtime.h>
#include <cuda_fp16.h>

// out[v] = sum over edges (u->v) of emb[u], D_FEAT = 64 fp32.
// R17: same plan as R16, but L2::evict_last is only legal on 256-bit loads
// on sm_103a -> restructure hot loads to ld.global.nc.L2::evict_last.v8.b32.
//  k1: prep (zero 12.8MB acc, 1 uint4/thread; convert emb->fp16, 32B load/thread)
//  k2: edge-parallel push, 4 threads per edge-quad x 32B chunk,
//      red.global.add.noftz.v4.f16x2 x2 per chunk, replica (e&1)
//  k3: combine 2 fp16 replicas -> fp32 out

#define N_NODES_MAX 50000
#define D_FEAT 64
#define N_REP 2

__device__ __half g_embh[N_NODES_MAX * D_FEAT];
__device__ __half g_acc[N_REP][N_NODES_MAX * D_FEAT];

// 32B load with L2 evict_last (keeps small reused tensors L2-resident).
__device__ __forceinline__ void ldg_v8_keep(const void* p, unsigned int r[8]) {
    asm volatile(
        "ld.global.nc.L2::evict_last.v8.b32 {%0,%1,%2,%3,%4,%5,%6,%7}, [%8];"
        : "=r"(r[0]), "=r"(r[1]), "=r"(r[2]), "=r"(r[3]),
          "=r"(r[4]), "=r"(r[5]), "=r"(r[6]), "=r"(r[7])
        : "l"(p));
}

// i < n_zero16: zero one uint4 (8 halves) of g_acc.
// i < n_conv:   convert 8 floats (one 32B load) -> 8 halves (one uint4 store).
__global__ void prep_kernel(const float* __restrict__ emb,
                            int n_conv, int n_zero16) {
    int i = blockIdx.x * blockDim.x + threadIdx.x;
    if (i < n_zero16) {
        reinterpret_cast<uint4*>(g_acc)[i] = make_uint4(0u, 0u, 0u, 0u);
    }
    if (i < n_conv) {
        unsigned int w[8];
        ldg_v8_keep(emb + (size_t)i * 8, w);
        float* f = reinterpret_cast<float*>(w);
        __half2 h0 = __floats2half2_rn(f[0], f[1]);
        __half2 h1 = __floats2half2_rn(f[2], f[3]);
        __half2 h2 = __floats2half2_rn(f[4], f[5]);
        __half2 h3 = __floats2half2_rn(f[6], f[7]);
        uint4 packed;
        packed.x = *reinterpret_cast<unsigned int*>(&h0);
        packed.y = *reinterpret_cast<unsigned int*>(&h1);
        packed.z = *reinterpret_cast<unsigned int*>(&h2);
        packed.w = *reinterpret_cast<unsigned int*>(&h3);
        reinterpret_cast<uint4*>(g_embh)[i] = packed;
    }
}

__device__ __forceinline__ void red_add_v4h2(__half* p, unsigned int a,
                                             unsigned int b, unsigned int c,
                                             unsigned int d) {
    asm volatile("red.global.add.noftz.v4.f16x2 [%0], {%1, %2, %3, %4};"
                 :: "l"(p), "r"(a), "r"(b), "r"(c), "r"(d) : "memory");
}

// 4 threads per edge quad; thread owns one 32B chunk (16 halves) of the
// 128B row for 4 edges.  One v8.b32 gather + two v4.f16x2 REDs per edge.
__global__ void edge_scatter_h2_kernel(const int* __restrict__ src,
                                       const int* __restrict__ dst,
                                       int n_edges) {
    long long t = (long long)blockIdx.x * blockDim.x + threadIdx.x;
    int q = (int)(t >> 2);     // edge-quad index
    int c = (int)(t & 3);      // 32B chunk within the 128B row
    int e0 = q * 4;
    if (e0 >= n_edges) return;

    const char* tbl = reinterpret_cast<const char*>(g_embh);

    if (e0 + 3 < n_edges) {
        int4 s = __ldg((const int4*)(src + e0));
        int4 d = __ldg((const int4*)(dst + e0));

        unsigned int v0[8], v1[8], v2[8], v3[8];
        // 4 independent 32B gather chains; evict_last keeps 6.4MB table hot.
        ldg_v8_keep(tbl + (long long)s.x * 128 + c * 32, v0);
        ldg_v8_keep(tbl + (long long)s.y * 128 + c * 32, v1);
        ldg_v8_keep(tbl + (long long)s.z * 128 + c * 32, v2);
        ldg_v8_keep(tbl + (long long)s.w * 128 + c * 32, v3);

        __half* p0 = g_acc[0] + ((long long)d.x * D_FEAT + c * 16);
        __half* p1 = g_acc[1] + ((long long)d.y * D_FEAT + c * 16);
        __half* p2 = g_acc[0] + ((long long)d.z * D_FEAT + c * 16);
        __half* p3 = g_acc[1] + ((long long)d.w * D_FEAT + c * 16);

        red_add_v4h2(p0,     v0[0], v0[1], v0[2], v0[3]);
        red_add_v4h2(p0 + 8, v0[4], v0[5], v0[6], v0[7]);
        red_add_v4h2(p1,     v1[0], v1[1], v1[2], v1[3]);
        red_add_v4h2(p1 + 8, v1[4], v1[5], v1[6], v1[7]);
        red_add_v4h2(p2,     v2[0], v2[1], v2[2], v2[3]);
        red_add_v4h2(p2 + 8, v2[4], v2[5], v2[6], v2[7]);
        red_add_v4h2(p3,     v3[0], v3[1], v3[2], v3[3]);
        red_add_v4h2(p3 + 8, v3[4], v3[5], v3[6], v3[7]);
    } else {
        for (int e = e0; e < n_edges; e++) {
            int s = src[e];
            int d = dst[e];
            unsigned int v[8];
            ldg_v8_keep(tbl + (long long)s * 128 + c * 32, v);
            __half* p = g_acc[e & 1] + ((long long)d * D_FEAT + c * 16);
            red_add_v4h2(p,     v[0], v[1], v[2], v[3]);
            red_add_v4h2(p + 8, v[4], v[5], v[6], v[7]);
        }
    }
}

// out fp32 = sum of 2 fp16 replicas.  Thread handles 8 floats.
__global__ void combine_kernel(float4* __restrict__ out, int n_grp8) {
    int i = blockIdx.x * blockDim.x + threadIdx.x;
    if (i >= n_grp8) return;

    float acc[8];
#pragma unroll
    for (int k = 0; k < 8; k++) acc[k] = 0.f;

#pragma unroll
    for (int r = 0; r < N_REP; r++) {
        uint4 v = __ldg(reinterpret_cast<const uint4*>(g_acc[r]) + i);
        const unsigned int w[4] = {v.x, v.y, v.z, v.w};
#pragma unroll
        for (int k = 0; k < 4; k++) {
            __half2 h = *reinterpret_cast<const __half2*>(&w[k]);
            float2 f = __half22float2(h);
            acc[2 * k + 0] += f.x;
            acc[2 * k + 1] += f.y;
        }
    }

    out[i * 2 + 0] = make_float4(acc[0], acc[1], acc[2], acc[3]);
    out[i * 2 + 1] = make_float4(acc[4], acc[5], acc[6], acc[7]);
}

extern "C" void kernel_launch(void* const* d_in, const int* in_sizes, int n_in,
                              void* d_out, int out_size) {
    const float* emb = (const float*)d_in[0];
    const int*   src = (const int*)d_in[1];
    const int*   dst = (const int*)d_in[2];

    int n_elems = in_sizes[0];            // n_nodes * 64 floats
    int n_edges = in_sizes[1];
    int n_nodes = out_size / D_FEAT;

    int n_conv   = n_elems / 8;                       // 400K threads convert
    int n_zero16 = (n_nodes * D_FEAT * N_REP) / 8;    // 800K uint4 zeroes
    int n_prep   = n_zero16 > n_conv ? n_zero16 : n_conv;

    prep_kernel<<<(n_prep + 255) / 256, 256>>>(emb, n_conv, n_zero16);

    int n_quads = (n_edges + 3) / 4;
    long long total_threads = (long long)n_quads * 4;
    int grid = (int)((total_threads + 255) / 256);
    edge_scatter_h2_kernel<<<grid, 256>>>(src, dst, n_edges);

    int n_grp8 = out_size / 8;
    combine_kernel<<<(n_grp8 + 255) / 256, 256>>>((float4*)d_out, n_grp8);
}